// round 9
// baseline (speedup 1.0000x reference)
#include <cuda_runtime.h>
#include <cuda_fp16.h>
#include <cstdint>

#define Bb 8
#define Nn 1024
#define Ff 256
#define Hh 4
#define Uu 256
#define BHt (Bb * Hh)

#define STRIDE 40   // smem row stride in halves (80B): 16B-row conflict-free for ldmatrix

// ---------------- device scratch (static, no allocation) ----------------
__device__ __half g_xh[(size_t)Bb * Nn * Ff];       // x split hi [b][n][f]
__device__ __half g_xl[(size_t)Bb * Nn * Ff];       // x split lo
__device__ __half g_vt[(size_t)BHt * Uu * Nn];      // h^T fp16 [bh][u][n]
__device__ __half g_wt_hi[Hh * Uu * Ff];            // W^T split fp16 [h][u][f]
__device__ __half g_wt_lo[Hh * Uu * Ff];
__device__ float g_srcp[2 * BHt * Nn];              // partial src dots [uhalf][bh*N+n]
__device__ float g_dstp[2 * BHt * Nn];
__device__ __half g_Qh[BHt * Nn];
__device__ __half g_Sh[BHt * Nn];
__device__ __half g_Dh[BHt * Nn];
__device__ __half g_Ph[BHt * Nn];
__device__ __half g_Rh[BHt * Nn];
__device__ __half g_Th[BHt * Nn];

// ---------------- PTX helpers ----------------
__device__ __forceinline__ void mma16816(float* c, const uint32_t* a, uint32_t b0, uint32_t b1) {
    asm volatile(
        "mma.sync.aligned.m16n8k16.row.col.f32.f16.f16.f32 "
        "{%0,%1,%2,%3}, {%4,%5,%6,%7}, {%8,%9}, {%0,%1,%2,%3};"
        : "+f"(c[0]), "+f"(c[1]), "+f"(c[2]), "+f"(c[3])
        : "r"(a[0]), "r"(a[1]), "r"(a[2]), "r"(a[3]), "r"(b0), "r"(b1));
}
__device__ __forceinline__ void ldm_x4(uint32_t* r, uint32_t addr) {
    asm volatile("ldmatrix.sync.aligned.m8n8.x4.shared.b16 {%0,%1,%2,%3}, [%4];"
                 : "=r"(r[0]), "=r"(r[1]), "=r"(r[2]), "=r"(r[3]) : "r"(addr));
}
__device__ __forceinline__ void cp16(uint32_t dst, const void* src) {
    asm volatile("cp.async.ca.shared.global [%0], [%1], 16;" :: "r"(dst), "l"(src));
}
__device__ __forceinline__ void cp_commit() { asm volatile("cp.async.commit_group;"); }
template <int N> __device__ __forceinline__ void cp_wait() {
    asm volatile("cp.async.wait_group %0;" :: "n"(N));
}

// ================== prep: split x into fp16 hi/lo ==================
__global__ __launch_bounds__(256) void prep_x_kernel(const float* __restrict__ x) {
    int idx = blockIdx.x * 256 + threadIdx.x;          // float4 index
    float4 v = ((const float4*)x)[idx];
    __half h0 = __float2half_rn(v.x), h1 = __float2half_rn(v.y);
    __half h2 = __float2half_rn(v.z), h3 = __float2half_rn(v.w);
    __half2 hi01 = __halves2half2(h0, h1), hi23 = __halves2half2(h2, h3);
    __half2 lo01 = __floats2half2_rn(v.x - __half2float(h0), v.y - __half2float(h1));
    __half2 lo23 = __floats2half2_rn(v.z - __half2float(h2), v.w - __half2float(h3));
    ((__half2*)g_xh)[idx * 2] = hi01;
    ((__half2*)g_xh)[idx * 2 + 1] = hi23;
    ((__half2*)g_xl)[idx * 2] = lo01;
    ((__half2*)g_xl)[idx * 2 + 1] = lo23;
}

// ================== prep: W^T split fp16 [h][u][f] ==================
__global__ __launch_bounds__(256) void prep_wt_kernel(const float* __restrict__ W) {
    int idx = blockIdx.x * 256 + threadIdx.x;
    int f = idx & 255, u = (idx >> 8) & 255, h = idx >> 16;
    float w = W[((size_t)(h * 256 + f)) * 256 + u];
    __half hi = __float2half_rn(w);
    __half lo = __float2half_rn(w - __half2float(hi));
    size_t o = ((size_t)(h * 256 + u)) * 256 + f;
    g_wt_hi[o] = hi;
    g_wt_lo[o] = lo;
}

// ================== proj: h = x @ W (fp16 3-term, ldmatrix + cp.async) ==================
// dyn smem: buf[2] x {Ah, Al, Wh, Wl} each 128 x STRIDE halves; sred at +81920
#define PBUF (4 * 128 * STRIDE * 2)                    // 40960 B per buffer
#define P_SMEM (2 * PBUF + 4096)

__global__ __launch_bounds__(256) void proj_mma_kernel(const float* __restrict__ a_src,
                                                       const float* __restrict__ a_dst) {
    extern __shared__ __align__(16) char dyn[];
    float* sred = (float*)(dyn + 2 * PBUF);            // [2][2][128]

    int tid = threadIdx.x;
    int warp = tid >> 5, lane = tid & 31;
    int warp_m = warp & 3, warp_n = warp >> 2;
    int bh = blockIdx.z, b = bh >> 2, h = bh & 3;
    int i0 = blockIdx.x * 128, u0 = blockIdx.y * 128;

    uint32_t smb = (uint32_t)__cvta_generic_to_shared(dyn);
    int row = tid >> 1, seg = tid & 1;

    auto issue = [&](int st, int bufi) {
        int f0 = st * 32;
        uint32_t base = smb + bufi * PBUF + row * (STRIDE * 2) + seg * 32;
        const __half* gA = g_xh + ((size_t)(b * Nn + i0 + row)) * Ff + f0 + seg * 16;
        const __half* gAl = g_xl + ((size_t)(b * Nn + i0 + row)) * Ff + f0 + seg * 16;
        const __half* gWh = g_wt_hi + ((size_t)(h * 256 + u0 + row)) * 256 + f0 + seg * 16;
        const __half* gWl = g_wt_lo + ((size_t)(h * 256 + u0 + row)) * 256 + f0 + seg * 16;
        cp16(base, gA);                 cp16(base + 16, gA + 8);
        cp16(base + 10240, gAl);        cp16(base + 10240 + 16, gAl + 8);
        cp16(base + 20480, gWh);        cp16(base + 20480 + 16, gWh + 8);
        cp16(base + 30720, gWl);        cp16(base + 30720 + 16, gWl + 8);
    };

    float acc[2][8][4];
#pragma unroll
    for (int mt = 0; mt < 2; mt++)
#pragma unroll
        for (int nt = 0; nt < 8; nt++)
#pragma unroll
            for (int q = 0; q < 4; q++) acc[mt][nt][q] = 0.f;

    issue(0, 0);
    cp_commit();

    uint32_t a_off = (uint32_t)(warp_m * 32 + (lane & 15)) * (STRIDE * 2) + ((lane >> 4) * 8) * 2;
    uint32_t b_off = (uint32_t)(warp_n * 64 + (lane & 7)) * (STRIDE * 2) + ((lane >> 3) * 8) * 2;

    for (int st = 0; st < 8; st++) {
        if (st < 7) { issue(st + 1, (st + 1) & 1); cp_commit(); cp_wait<1>(); }
        else cp_wait<0>();
        __syncthreads();

        uint32_t bb = smb + (st & 1) * PBUF;
        uint32_t aH[2][2][4], aL[2][2][4];
#pragma unroll
        for (int mt = 0; mt < 2; mt++)
#pragma unroll
            for (int kk = 0; kk < 2; kk++) {
                uint32_t ad = bb + a_off + mt * 16 * (STRIDE * 2) + kk * 32;
                ldm_x4(aH[mt][kk], ad);
                ldm_x4(aL[mt][kk], ad + 10240);
            }
#pragma unroll
        for (int nt = 0; nt < 8; nt++) {
            uint32_t bH[4], bL[4];
            uint32_t bd = bb + 20480 + b_off + nt * 8 * (STRIDE * 2);
            ldm_x4(bH, bd);
            ldm_x4(bL, bd + 10240);
#pragma unroll
            for (int kk = 0; kk < 2; kk++)
#pragma unroll
                for (int mt = 0; mt < 2; mt++) {
                    mma16816(acc[mt][nt], aH[mt][kk], bH[2 * kk], bH[2 * kk + 1]);
                    mma16816(acc[mt][nt], aL[mt][kk], bH[2 * kk], bH[2 * kk + 1]);
                    mma16816(acc[mt][nt], aH[mt][kk], bL[2 * kk], bL[2 * kk + 1]);
                }
        }
        __syncthreads();
    }

    // ---- epilogue A: partial src/dst dots over this CTA's 128 u-columns ----
    {
        float s1[4] = {0.f, 0.f, 0.f, 0.f};
        float s2[4] = {0.f, 0.f, 0.f, 0.f};
#pragma unroll
        for (int nt = 0; nt < 8; nt++) {
            int u = u0 + warp_n * 64 + nt * 8 + (lane & 3) * 2;
            float2 as = *(const float2*)&a_src[h * 256 + u];
            float2 ad = *(const float2*)&a_dst[h * 256 + u];
#pragma unroll
            for (int mt = 0; mt < 2; mt++) {
                s1[mt * 2 + 0] += acc[mt][nt][0] * as.x + acc[mt][nt][1] * as.y;
                s1[mt * 2 + 1] += acc[mt][nt][2] * as.x + acc[mt][nt][3] * as.y;
                s2[mt * 2 + 0] += acc[mt][nt][0] * ad.x + acc[mt][nt][1] * ad.y;
                s2[mt * 2 + 1] += acc[mt][nt][2] * ad.x + acc[mt][nt][3] * ad.y;
            }
        }
#pragma unroll
        for (int q = 0; q < 4; q++) {
            s1[q] += __shfl_xor_sync(0xffffffffu, s1[q], 1);
            s1[q] += __shfl_xor_sync(0xffffffffu, s1[q], 2);
            s2[q] += __shfl_xor_sync(0xffffffffu, s2[q], 1);
            s2[q] += __shfl_xor_sync(0xffffffffu, s2[q], 2);
        }
        if ((lane & 3) == 0) {
#pragma unroll
            for (int q = 0; q < 4; q++) {
                int r = warp_m * 32 + (q >> 1) * 16 + (q & 1) * 8 + (lane >> 2);
                sred[(0 * 2 + warp_n) * 128 + r] = s1[q];
                sred[(2 + warp_n) * 128 + r] = s2[q];
            }
        }
    }
    __syncthreads();
    if (tid < 128) {
        size_t o = (size_t)blockIdx.y * (BHt * Nn) + bh * Nn + i0 + tid;
        g_srcp[o] = sred[0 * 128 + tid] + sred[1 * 128 + tid];
        g_dstp[o] = sred[2 * 128 + tid] + sred[3 * 128 + tid];
    }
    __syncthreads();

    // ---- epilogue B: fp16 transpose restage -> g_vt [u][n] ----
    __half (*tr)[136] = (__half (*)[136])dyn;
#pragma unroll
    for (int mt = 0; mt < 2; mt++) {
        int i_loc = warp_m * 32 + mt * 16 + (lane >> 2);
#pragma unroll
        for (int nt = 0; nt < 8; nt++) {
            int u_loc = warp_n * 64 + nt * 8 + (lane & 3) * 2;
            tr[u_loc][i_loc]         = __float2half_rn(acc[mt][nt][0]);
            tr[u_loc + 1][i_loc]     = __float2half_rn(acc[mt][nt][1]);
            tr[u_loc][i_loc + 8]     = __float2half_rn(acc[mt][nt][2]);
            tr[u_loc + 1][i_loc + 8] = __float2half_rn(acc[mt][nt][3]);
        }
    }
    __syncthreads();
    {
        const float4* srcp = (const float4*)&tr[row][seg * 64];
        float4* dstp = (float4*)&g_vt[((size_t)bh * Uu + u0 + row) * Nn + i0 + seg * 64];
#pragma unroll
        for (int k = 0; k < 8; k++) dstp[k] = srcp[k];
    }
}

// ================== prep: combine partials, P/Q/R/S/thr fp16 per (b,h) ==================
__global__ __launch_bounds__(1024) void prep_pqrs_kernel() {
    __shared__ float red[1024];
    int bh = blockIdx.x, tid = threadIdx.x;
    int row = bh * Nn + tid;
    float d = g_dstp[row] + g_dstp[BHt * Nn + row];
    float sv = g_srcp[row] + g_srcp[BHt * Nn + row];
    red[tid] = d;
    __syncthreads();
    for (int s = 512; s > 0; s >>= 1) {
        if (tid < s) red[tid] = fmaxf(red[tid], red[tid + s]);
        __syncthreads();
    }
    float dmax = red[0];
    g_Qh[row] = __float2half_rn(__expf(d - dmax));
    g_Sh[row] = __float2half_rn(__expf(0.2f * (d - dmax)));
    g_Dh[row] = __float2half_rn(d);
    float T = sv + dmax;
    float m = fmaxf(T, 0.2f * T);
    g_Ph[row] = __float2half_rn(__expf(T - m));
    g_Rh[row] = __float2half_rn(__expf(0.2f * T - m));
    g_Th[row] = __float2half_rn(-sv);
}

// ================== attention: half2 weight-gen + ldmatrix V + cp.async ==================
__global__ __launch_bounds__(256) void attn_mma_kernel(float* __restrict__ out) {
    __shared__ __align__(16) __half VT[2][128][STRIDE];
    __shared__ __half Dsh[Nn], Qsh[Nn], Ssh[Nn];
    __shared__ __half Pn[128], Rn[128], Tn[128];

    int tid = threadIdx.x;
    int warp = tid >> 5, lane = tid & 31;
    int warp_m = warp & 3, warp_n = warp >> 2;
    int bh = blockIdx.z, b = bh >> 2, h = bh & 3;
    int i0 = blockIdx.x * 128, u0 = blockIdx.y * 128;

    for (int j = tid; j < Nn; j += 256) {
        Dsh[j] = g_Dh[bh * Nn + j];
        Qsh[j] = g_Qh[bh * Nn + j];
        Ssh[j] = g_Sh[bh * Nn + j];
    }
    if (tid < 128) {
        Pn[tid] = g_Ph[bh * Nn + i0 + tid];
        Rn[tid] = g_Rh[bh * Nn + i0 + tid];
        Tn[tid] = g_Th[bh * Nn + i0 + tid];
    }

    int row = tid >> 1, seg = tid & 1;
    uint32_t vt0 = (uint32_t)__cvta_generic_to_shared(&VT[0][0][0]);
    const uint32_t VBUF = 128 * STRIDE * 2;

    auto issue = [&](int st, int bufi) {
        int j0 = st * 32;
        uint32_t d = vt0 + bufi * VBUF + row * (STRIDE * 2) + seg * 32;
        const __half* g = g_vt + ((size_t)bh * Uu + u0 + row) * Nn + j0 + seg * 16;
        cp16(d, g);
        cp16(d + 16, g + 8);
    };

    float acc[2][8][4];
#pragma unroll
    for (int mt = 0; mt < 2; mt++)
#pragma unroll
        for (int nt = 0; nt < 8; nt++)
#pragma unroll
            for (int q = 0; q < 4; q++) acc[mt][nt][q] = 0.f;
    float rs[4] = {0.f, 0.f, 0.f, 0.f};

    issue(0, 0);
    cp_commit();
    __syncthreads();   // Pn/Rn/Tn visible

    __half2 Pv[4], Rv[4], Tv[4];
#pragma unroll
    for (int q = 0; q < 4; q++) {
        int r = warp_m * 32 + (q >> 1) * 16 + (q & 1) * 8 + (lane >> 2);
        Pv[q] = __half2half2(Pn[r]);
        Rv[q] = __half2half2(Rn[r]);
        Tv[q] = __half2half2(Tn[r]);
    }

    uint32_t b_off = (uint32_t)(warp_n * 64 + (lane & 7)) * (STRIDE * 2) + ((lane >> 3) * 8) * 2;

    for (int st = 0; st < 32; st++) {
        int j0 = st * 32;
        if (st < 31) { issue(st + 1, (st + 1) & 1); cp_commit(); cp_wait<1>(); }
        else cp_wait<0>();
        __syncthreads();

        uint32_t bb = vt0 + (st & 1) * VBUF;
        uint32_t bfr[8][4];
#pragma unroll
        for (int nt = 0; nt < 8; nt++)
            ldm_x4(bfr[nt], bb + b_off + nt * 8 * (STRIDE * 2));

#pragma unroll
        for (int kk = 0; kk < 2; kk++) {
            int c = j0 + kk * 16 + (lane & 3) * 2;
            __half2 Qa = *(const __half2*)&Qsh[c], Qb = *(const __half2*)&Qsh[c + 8];
            __half2 Sa = *(const __half2*)&Ssh[c], Sb = *(const __half2*)&Ssh[c + 8];
            __half2 Da = *(const __half2*)&Dsh[c], Db = *(const __half2*)&Dsh[c + 8];

            uint32_t aW[2][4];
#pragma unroll
            for (int mt = 0; mt < 2; mt++) {
#pragma unroll
                for (int dq = 0; dq < 2; dq++) {
                    int q = mt * 2 + dq;
                    __half2 mA = __hge2(Da, Tv[q]);
                    __half2 wPa = __hmul2(Pv[q], Qa);
                    __half2 wRa = __hmul2(Rv[q], Sa);
                    __half2 wa = __hfma2(__hsub2(wPa, wRa), mA, wRa);
                    __half2 mB = __hge2(Db, Tv[q]);
                    __half2 wPb = __hmul2(Pv[q], Qb);
                    __half2 wRb = __hmul2(Rv[q], Sb);
                    __half2 wb = __hfma2(__hsub2(wPb, wRb), mB, wRb);
                    aW[mt][dq]     = *reinterpret_cast<uint32_t*>(&wa);
                    aW[mt][dq + 2] = *reinterpret_cast<uint32_t*>(&wb);
                    __half2 hsum = __hadd2(wa, wb);
                    float2 f = __half22float2(hsum);
                    rs[q] += f.x + f.y;
                }
            }
#pragma unroll
            for (int nt = 0; nt < 8; nt++)
#pragma unroll
                for (int mt = 0; mt < 2; mt++)
                    mma16816(acc[mt][nt], aW[mt], bfr[nt][2 * kk], bfr[nt][2 * kk + 1]);
        }
        __syncthreads();
    }

#pragma unroll
    for (int q = 0; q < 4; q++) {
        rs[q] += __shfl_xor_sync(0xffffffffu, rs[q], 1);
        rs[q] += __shfl_xor_sync(0xffffffffu, rs[q], 2);
        rs[q] = 1.0f / rs[q];
    }

#pragma unroll
    for (int mt = 0; mt < 2; mt++) {
        int i_lo = i0 + warp_m * 32 + mt * 16 + (lane >> 2);
        float inv0 = rs[mt * 2], inv1 = rs[mt * 2 + 1];
#pragma unroll
        for (int nt = 0; nt < 8; nt++) {
            int u = u0 + warp_n * 64 + nt * 8 + (lane & 3) * 2;
            size_t o0 = ((size_t)(b * Nn + i_lo)) * (Hh * Uu) + h * Uu + u;
            size_t o1 = ((size_t)(b * Nn + i_lo + 8)) * (Hh * Uu) + h * Uu + u;
            *(float2*)&out[o0] = make_float2(acc[mt][nt][0] * inv0, acc[mt][nt][1] * inv0);
            *(float2*)&out[o1] = make_float2(acc[mt][nt][2] * inv1, acc[mt][nt][3] * inv1);
        }
    }
}

// ---------------------------------------------------------------------------
extern "C" void kernel_launch(void* const* d_in, const int* in_sizes, int n_in,
                              void* d_out, int out_size) {
    (void)in_sizes; (void)n_in; (void)out_size;
    const float* x     = (const float*)d_in[0];
    const float* W     = (const float*)d_in[1];
    const float* a_src = (const float*)d_in[2];
    const float* a_dst = (const float*)d_in[3];
    float* out = (float*)d_out;

    cudaFuncSetAttribute(proj_mma_kernel, cudaFuncAttributeMaxDynamicSharedMemorySize, P_SMEM);

    prep_x_kernel<<<(Bb * Nn * Ff) / 1024, 256>>>(x);
    prep_wt_kernel<<<(Hh * Uu * Ff) / 256, 256>>>(W);
    proj_mma_kernel<<<dim3(8, 2, BHt), 256, P_SMEM>>>(a_src, a_dst);
    prep_pqrs_kernel<<<BHt, 1024>>>();
    attn_mma_kernel<<<dim3(8, 2, BHt), 256>>>(out);
}

// round 10
// speedup vs baseline: 1.0119x; 1.0119x over previous
#include <cuda_runtime.h>
#include <cuda_fp16.h>
#include <cstdint>

#define Bb 8
#define Nn 1024
#define Ff 256
#define Hh 4
#define Uu 256
#define BHt (Bb * Hh)

#define STRIDE 40   // smem row stride in halves (80B): conflict-free for ldmatrix

// ---------------- device scratch (static, no allocation) ----------------
__device__ __half g_xh[(size_t)Bb * Nn * Ff];       // x split hi [b][n][f]
__device__ __half g_xl[(size_t)Bb * Nn * Ff];       // x split lo
__device__ __half g_vt[(size_t)BHt * Uu * Nn];      // h^T fp16 [bh][u][n]
__device__ __half g_wt_hi[Hh * Uu * Ff];            // W^T split fp16 [h][u][f]
__device__ __half g_wt_lo[Hh * Uu * Ff];
__device__ float g_srcp[2 * BHt * Nn];
__device__ float g_dstp[2 * BHt * Nn];
__device__ __half g_Qh[BHt * Nn];
__device__ __half g_Sh[BHt * Nn];
__device__ __half g_Dh[BHt * Nn];
__device__ __half g_Ph[BHt * Nn];
__device__ __half g_Rh[BHt * Nn];
__device__ __half g_Th[BHt * Nn];

// ---------------- PTX helpers ----------------
__device__ __forceinline__ void mma16816(float* c, const uint32_t* a, uint32_t b0, uint32_t b1) {
    asm volatile(
        "mma.sync.aligned.m16n8k16.row.col.f32.f16.f16.f32 "
        "{%0,%1,%2,%3}, {%4,%5,%6,%7}, {%8,%9}, {%0,%1,%2,%3};"
        : "+f"(c[0]), "+f"(c[1]), "+f"(c[2]), "+f"(c[3])
        : "r"(a[0]), "r"(a[1]), "r"(a[2]), "r"(a[3]), "r"(b0), "r"(b1));
}
__device__ __forceinline__ void ldm_x4(uint32_t* r, uint32_t addr) {
    asm volatile("ldmatrix.sync.aligned.m8n8.x4.shared.b16 {%0,%1,%2,%3}, [%4];"
                 : "=r"(r[0]), "=r"(r[1]), "=r"(r[2]), "=r"(r[3]) : "r"(addr));
}
__device__ __forceinline__ void cp16(uint32_t dst, const void* src) {
    asm volatile("cp.async.ca.shared.global [%0], [%1], 16;" :: "r"(dst), "l"(src));
}
__device__ __forceinline__ void cp_commit() { asm volatile("cp.async.commit_group;"); }
template <int N> __device__ __forceinline__ void cp_wait() {
    asm volatile("cp.async.wait_group %0;" :: "n"(N));
}

// ================== prep: split x into fp16 hi/lo ==================
__global__ __launch_bounds__(256) void prep_x_kernel(const float* __restrict__ x) {
    int idx = blockIdx.x * 256 + threadIdx.x;
    float4 v = ((const float4*)x)[idx];
    __half h0 = __float2half_rn(v.x), h1 = __float2half_rn(v.y);
    __half h2 = __float2half_rn(v.z), h3 = __float2half_rn(v.w);
    __half2 hi01 = __halves2half2(h0, h1), hi23 = __halves2half2(h2, h3);
    __half2 lo01 = __floats2half2_rn(v.x - __half2float(h0), v.y - __half2float(h1));
    __half2 lo23 = __floats2half2_rn(v.z - __half2float(h2), v.w - __half2float(h3));
    ((__half2*)g_xh)[idx * 2] = hi01;
    ((__half2*)g_xh)[idx * 2 + 1] = hi23;
    ((__half2*)g_xl)[idx * 2] = lo01;
    ((__half2*)g_xl)[idx * 2 + 1] = lo23;
}

// ================== prep: W^T split fp16 [h][u][f] ==================
__global__ __launch_bounds__(256) void prep_wt_kernel(const float* __restrict__ W) {
    int idx = blockIdx.x * 256 + threadIdx.x;
    int f = idx & 255, u = (idx >> 8) & 255, h = idx >> 16;
    float w = W[((size_t)(h * 256 + f)) * 256 + u];
    __half hi = __float2half_rn(w);
    __half lo = __float2half_rn(w - __half2float(hi));
    size_t o = ((size_t)(h * 256 + u)) * 256 + f;
    g_wt_hi[o] = hi;
    g_wt_lo[o] = lo;
}

// ================== proj: h = x @ W (fp16 3-term, ldmatrix + cp.async) ==================
#define PBUF (4 * 128 * STRIDE * 2)                    // 40960 B per buffer
#define P_SMEM (2 * PBUF + 4096)

__global__ __launch_bounds__(256) void proj_mma_kernel(const float* __restrict__ a_src,
                                                       const float* __restrict__ a_dst) {
    extern __shared__ __align__(16) char dyn[];
    float* sred = (float*)(dyn + 2 * PBUF);

    int tid = threadIdx.x;
    int warp = tid >> 5, lane = tid & 31;
    int warp_m = warp & 3, warp_n = warp >> 2;
    int bh = blockIdx.z, b = bh >> 2, h = bh & 3;
    int i0 = blockIdx.x * 128, u0 = blockIdx.y * 128;

    uint32_t smb = (uint32_t)__cvta_generic_to_shared(dyn);
    int row = tid >> 1, seg = tid & 1;

    auto issue = [&](int st, int bufi) {
        int f0 = st * 32;
        uint32_t base = smb + bufi * PBUF + row * (STRIDE * 2) + seg * 32;
        const __half* gA = g_xh + ((size_t)(b * Nn + i0 + row)) * Ff + f0 + seg * 16;
        const __half* gAl = g_xl + ((size_t)(b * Nn + i0 + row)) * Ff + f0 + seg * 16;
        const __half* gWh = g_wt_hi + ((size_t)(h * 256 + u0 + row)) * 256 + f0 + seg * 16;
        const __half* gWl = g_wt_lo + ((size_t)(h * 256 + u0 + row)) * 256 + f0 + seg * 16;
        cp16(base, gA);                 cp16(base + 16, gA + 8);
        cp16(base + 10240, gAl);        cp16(base + 10240 + 16, gAl + 8);
        cp16(base + 20480, gWh);        cp16(base + 20480 + 16, gWh + 8);
        cp16(base + 30720, gWl);        cp16(base + 30720 + 16, gWl + 8);
    };

    float acc[2][8][4];
#pragma unroll
    for (int mt = 0; mt < 2; mt++)
#pragma unroll
        for (int nt = 0; nt < 8; nt++)
#pragma unroll
            for (int q = 0; q < 4; q++) acc[mt][nt][q] = 0.f;

    issue(0, 0);
    cp_commit();

    uint32_t a_off = (uint32_t)(warp_m * 32 + (lane & 15)) * (STRIDE * 2) + ((lane >> 4) * 8) * 2;
    uint32_t b_off = (uint32_t)(warp_n * 64 + (lane & 7)) * (STRIDE * 2) + ((lane >> 3) * 8) * 2;

    for (int st = 0; st < 8; st++) {
        if (st < 7) { issue(st + 1, (st + 1) & 1); cp_commit(); cp_wait<1>(); }
        else cp_wait<0>();
        __syncthreads();

        uint32_t bb = smb + (st & 1) * PBUF;
        uint32_t aH[2][2][4], aL[2][2][4];
#pragma unroll
        for (int mt = 0; mt < 2; mt++)
#pragma unroll
            for (int kk = 0; kk < 2; kk++) {
                uint32_t ad = bb + a_off + mt * 16 * (STRIDE * 2) + kk * 32;
                ldm_x4(aH[mt][kk], ad);
                ldm_x4(aL[mt][kk], ad + 10240);
            }
#pragma unroll
        for (int nt = 0; nt < 8; nt++) {
            uint32_t bH[4], bL[4];
            uint32_t bd = bb + 20480 + b_off + nt * 8 * (STRIDE * 2);
            ldm_x4(bH, bd);
            ldm_x4(bL, bd + 10240);
#pragma unroll
            for (int kk = 0; kk < 2; kk++)
#pragma unroll
                for (int mt = 0; mt < 2; mt++) {
                    mma16816(acc[mt][nt], aH[mt][kk], bH[2 * kk], bH[2 * kk + 1]);
                    mma16816(acc[mt][nt], aL[mt][kk], bH[2 * kk], bH[2 * kk + 1]);
                    mma16816(acc[mt][nt], aH[mt][kk], bL[2 * kk], bL[2 * kk + 1]);
                }
        }
        __syncthreads();
    }

    // ---- epilogue A: partial src/dst dots ----
    {
        float s1[4] = {0.f, 0.f, 0.f, 0.f};
        float s2[4] = {0.f, 0.f, 0.f, 0.f};
#pragma unroll
        for (int nt = 0; nt < 8; nt++) {
            int u = u0 + warp_n * 64 + nt * 8 + (lane & 3) * 2;
            float2 as = *(const float2*)&a_src[h * 256 + u];
            float2 ad = *(const float2*)&a_dst[h * 256 + u];
#pragma unroll
            for (int mt = 0; mt < 2; mt++) {
                s1[mt * 2 + 0] += acc[mt][nt][0] * as.x + acc[mt][nt][1] * as.y;
                s1[mt * 2 + 1] += acc[mt][nt][2] * as.x + acc[mt][nt][3] * as.y;
                s2[mt * 2 + 0] += acc[mt][nt][0] * ad.x + acc[mt][nt][1] * ad.y;
                s2[mt * 2 + 1] += acc[mt][nt][2] * ad.x + acc[mt][nt][3] * ad.y;
            }
        }
#pragma unroll
        for (int q = 0; q < 4; q++) {
            s1[q] += __shfl_xor_sync(0xffffffffu, s1[q], 1);
            s1[q] += __shfl_xor_sync(0xffffffffu, s1[q], 2);
            s2[q] += __shfl_xor_sync(0xffffffffu, s2[q], 1);
            s2[q] += __shfl_xor_sync(0xffffffffu, s2[q], 2);
        }
        if ((lane & 3) == 0) {
#pragma unroll
            for (int q = 0; q < 4; q++) {
                int r = warp_m * 32 + (q >> 1) * 16 + (q & 1) * 8 + (lane >> 2);
                sred[(0 * 2 + warp_n) * 128 + r] = s1[q];
                sred[(2 + warp_n) * 128 + r] = s2[q];
            }
        }
    }
    __syncthreads();
    if (tid < 128) {
        size_t o = (size_t)blockIdx.y * (BHt * Nn) + bh * Nn + i0 + tid;
        g_srcp[o] = sred[0 * 128 + tid] + sred[1 * 128 + tid];
        g_dstp[o] = sred[2 * 128 + tid] + sred[3 * 128 + tid];
    }
    __syncthreads();

    // ---- epilogue B: fp16 transpose restage -> g_vt [u][n] ----
    __half (*tr)[136] = (__half (*)[136])dyn;
#pragma unroll
    for (int mt = 0; mt < 2; mt++) {
        int i_loc = warp_m * 32 + mt * 16 + (lane >> 2);
#pragma unroll
        for (int nt = 0; nt < 8; nt++) {
            int u_loc = warp_n * 64 + nt * 8 + (lane & 3) * 2;
            tr[u_loc][i_loc]         = __float2half_rn(acc[mt][nt][0]);
            tr[u_loc + 1][i_loc]     = __float2half_rn(acc[mt][nt][1]);
            tr[u_loc][i_loc + 8]     = __float2half_rn(acc[mt][nt][2]);
            tr[u_loc + 1][i_loc + 8] = __float2half_rn(acc[mt][nt][3]);
        }
    }
    __syncthreads();
    {
        const float4* srcp = (const float4*)&tr[row][seg * 64];
        float4* dstp = (float4*)&g_vt[((size_t)bh * Uu + u0 + row) * Nn + i0 + seg * 64];
#pragma unroll
        for (int k = 0; k < 8; k++) dstp[k] = srcp[k];
    }
}

// ================== prep: combine partials, P/Q/R/S/thr fp16 per (b,h) ==================
__global__ __launch_bounds__(1024) void prep_pqrs_kernel() {
    __shared__ float red[1024];
    int bh = blockIdx.x, tid = threadIdx.x;
    int row = bh * Nn + tid;
    float d = g_dstp[row] + g_dstp[BHt * Nn + row];
    float sv = g_srcp[row] + g_srcp[BHt * Nn + row];
    red[tid] = d;
    __syncthreads();
    for (int s = 512; s > 0; s >>= 1) {
        if (tid < s) red[tid] = fmaxf(red[tid], red[tid + s]);
        __syncthreads();
    }
    float dmax = red[0];
    g_Qh[row] = __float2half_rn(__expf(d - dmax));
    g_Sh[row] = __float2half_rn(__expf(0.2f * (d - dmax)));
    g_Dh[row] = __float2half_rn(d);
    float T = sv + dmax;
    float m = fmaxf(T, 0.2f * T);
    g_Ph[row] = __float2half_rn(__expf(T - m));
    g_Rh[row] = __float2half_rn(__expf(0.2f * T - m));
    g_Th[row] = __float2half_rn(-sv);
}

// ================== attention: one CTA per (i-tile, bh), full 256 u ==================
// dyn smem: VT 3 bufs x 256 x STRIDE halves (61440 B) + D/Q/S (6144) + P/R/T (768)
#define VBUF (256 * STRIDE * 2)
#define A_SMEM (3 * VBUF + 6144 + 768)

__global__ __launch_bounds__(256) void attn_mma_kernel(float* __restrict__ out) {
    extern __shared__ __align__(16) char adyn[];
    __half* Dsh = (__half*)(adyn + 3 * VBUF);
    __half* Qsh = Dsh + Nn;
    __half* Ssh = Qsh + Nn;
    __half* Pn = Ssh + Nn;
    __half* Rn = Pn + 128;
    __half* Tn = Rn + 128;

    int tid = threadIdx.x;
    int warp = tid >> 5, lane = tid & 31;
    int warp_m = warp & 3, warp_n = warp >> 2;
    int bh = blockIdx.z, b = bh >> 2, h = bh & 3;
    int i0 = blockIdx.x * 128;

    for (int j = tid; j < Nn; j += 256) {
        Dsh[j] = g_Dh[bh * Nn + j];
        Qsh[j] = g_Qh[bh * Nn + j];
        Ssh[j] = g_Sh[bh * Nn + j];
    }
    if (tid < 128) {
        Pn[tid] = g_Ph[bh * Nn + i0 + tid];
        Rn[tid] = g_Rh[bh * Nn + i0 + tid];
        Tn[tid] = g_Th[bh * Nn + i0 + tid];
    }

    int row2 = tid >> 1, seg = tid & 1;
    uint32_t vt0 = (uint32_t)__cvta_generic_to_shared(adyn);

    auto issue = [&](int st, int bufi) {
        int j0 = st * 32;
#pragma unroll
        for (int rr = 0; rr < 2; rr++) {
            int r = row2 + rr * 128;
            uint32_t d = vt0 + bufi * VBUF + r * (STRIDE * 2) + seg * 32;
            const __half* g = g_vt + ((size_t)bh * Uu + r) * Nn + j0 + seg * 16;
            cp16(d, g);
            cp16(d + 16, g + 8);
        }
    };

    float acc[2][16][4];
#pragma unroll
    for (int mt = 0; mt < 2; mt++)
#pragma unroll
        for (int nt = 0; nt < 16; nt++)
#pragma unroll
            for (int q = 0; q < 4; q++) acc[mt][nt][q] = 0.f;
    float rs[4] = {0.f, 0.f, 0.f, 0.f};

    issue(0, 0); cp_commit();
    issue(1, 1); cp_commit();
    __syncthreads();   // Dsh/Pn visible

    __half2 Pv[4], Rv[4], Tv[4];
#pragma unroll
    for (int q = 0; q < 4; q++) {
        int r = warp_m * 32 + (q >> 1) * 16 + (q & 1) * 8 + (lane >> 2);
        Pv[q] = __half2half2(Pn[r]);
        Rv[q] = __half2half2(Rn[r]);
        Tv[q] = __half2half2(Tn[r]);
    }

    uint32_t b_off = (uint32_t)(warp_n * 128 + (lane & 7)) * (STRIDE * 2) + ((lane >> 3) * 8) * 2;

    for (int st = 0; st < 32; st++) {
        int j0 = st * 32;
        if (st + 1 < 32) cp_wait<1>(); else cp_wait<0>();
        __syncthreads();                       // stage st visible; all done with buf (st+2)%3
        if (st + 2 < 32) { issue(st + 2, (st + 2) % 3); cp_commit(); }

        uint32_t bb = vt0 + (st % 3) * VBUF;

        // weight-gen: aW[kk][mt][4]
        uint32_t aW[2][2][4];
#pragma unroll
        for (int kk = 0; kk < 2; kk++) {
            int c = j0 + kk * 16 + (lane & 3) * 2;
            __half2 Qa = *(const __half2*)&Qsh[c], Qb = *(const __half2*)&Qsh[c + 8];
            __half2 Sa = *(const __half2*)&Ssh[c], Sb = *(const __half2*)&Ssh[c + 8];
            __half2 Da = *(const __half2*)&Dsh[c], Db = *(const __half2*)&Dsh[c + 8];
#pragma unroll
            for (int mt = 0; mt < 2; mt++) {
#pragma unroll
                for (int dq = 0; dq < 2; dq++) {
                    int q = mt * 2 + dq;
                    __half2 mA = __hge2(Da, Tv[q]);
                    __half2 wPa = __hmul2(Pv[q], Qa);
                    __half2 wRa = __hmul2(Rv[q], Sa);
                    __half2 wa = __hfma2(__hsub2(wPa, wRa), mA, wRa);
                    __half2 mB = __hge2(Db, Tv[q]);
                    __half2 wPb = __hmul2(Pv[q], Qb);
                    __half2 wRb = __hmul2(Rv[q], Sb);
                    __half2 wb = __hfma2(__hsub2(wPb, wRb), mB, wRb);
                    aW[kk][mt][dq]     = *reinterpret_cast<uint32_t*>(&wa);
                    aW[kk][mt][dq + 2] = *reinterpret_cast<uint32_t*>(&wb);
                    __half2 hsum = __hadd2(wa, wb);
                    float2 f = __half22float2(hsum);
                    rs[q] += f.x + f.y;
                }
            }
        }

#pragma unroll
        for (int nt = 0; nt < 16; nt++) {
            uint32_t bfr[4];
            ldm_x4(bfr, bb + b_off + nt * 8 * (STRIDE * 2));
#pragma unroll
            for (int kk = 0; kk < 2; kk++)
#pragma unroll
                for (int mt = 0; mt < 2; mt++)
                    mma16816(acc[mt][nt], aW[kk][mt], bfr[2 * kk], bfr[2 * kk + 1]);
        }
    }

#pragma unroll
    for (int q = 0; q < 4; q++) {
        rs[q] += __shfl_xor_sync(0xffffffffu, rs[q], 1);
        rs[q] += __shfl_xor_sync(0xffffffffu, rs[q], 2);
        rs[q] = 1.0f / rs[q];
    }

#pragma unroll
    for (int mt = 0; mt < 2; mt++) {
        int i_lo = i0 + warp_m * 32 + mt * 16 + (lane >> 2);
        float inv0 = rs[mt * 2], inv1 = rs[mt * 2 + 1];
#pragma unroll
        for (int nt = 0; nt < 16; nt++) {
            int u = warp_n * 128 + nt * 8 + (lane & 3) * 2;
            size_t o0 = ((size_t)(b * Nn + i_lo)) * (Hh * Uu) + h * Uu + u;
            size_t o1 = ((size_t)(b * Nn + i_lo + 8)) * (Hh * Uu) + h * Uu + u;
            *(float2*)&out[o0] = make_float2(acc[mt][nt][0] * inv0, acc[mt][nt][1] * inv0);
            *(float2*)&out[o1] = make_float2(acc[mt][nt][2] * inv1, acc[mt][nt][3] * inv1);
        }
    }
}

// ---------------------------------------------------------------------------
extern "C" void kernel_launch(void* const* d_in, const int* in_sizes, int n_in,
                              void* d_out, int out_size) {
    (void)in_sizes; (void)n_in; (void)out_size;
    const float* x     = (const float*)d_in[0];
    const float* W     = (const float*)d_in[1];
    const float* a_src = (const float*)d_in[2];
    const float* a_dst = (const float*)d_in[3];
    float* out = (float*)d_out;

    cudaFuncSetAttribute(proj_mma_kernel, cudaFuncAttributeMaxDynamicSharedMemorySize, P_SMEM);
    cudaFuncSetAttribute(attn_mma_kernel, cudaFuncAttributeMaxDynamicSharedMemorySize, A_SMEM);

    prep_x_kernel<<<(Bb * Nn * Ff) / 1024, 256>>>(x);
    prep_wt_kernel<<<(Hh * Uu * Ff) / 256, 256>>>(W);
    proj_mma_kernel<<<dim3(8, 2, BHt), 256, P_SMEM>>>(a_src, a_dst);
    prep_pqrs_kernel<<<BHt, 1024>>>();
    attn_mma_kernel<<<dim3(8, 1, BHt), 256, A_SMEM>>>(out);
}

// round 11
// speedup vs baseline: 1.0852x; 1.0724x over previous
#include <cuda_runtime.h>
#include <cuda_fp16.h>
#include <cstdint>

#define Bb 8
#define Nn 1024
#define Ff 256
#define Hh 4
#define Uu 256
#define BHt (Bb * Hh)

#define STRIDE 40   // smem row stride in halves (80B): conflict-free for ldmatrix

// ---------------- device scratch (static, no allocation) ----------------
__device__ __half g_xh[(size_t)Bb * Nn * Ff];       // x fp16 [b][n][f]
__device__ __half g_vt[(size_t)BHt * Uu * Nn];      // h^T fp16 [bh][u][n]
__device__ __half g_wt_hi[Hh * Uu * Ff];            // W^T split fp16 [h][u][f]
__device__ __half g_wt_lo[Hh * Uu * Ff];
__device__ float g_srcp[2 * BHt * Nn];
__device__ float g_dstp[2 * BHt * Nn];
__device__ __half g_Qh[BHt * Nn];
__device__ __half g_Sh[BHt * Nn];
__device__ __half g_Dh[BHt * Nn];
__device__ __half g_Ph[BHt * Nn];
__device__ __half g_Rh[BHt * Nn];
__device__ __half g_Th[BHt * Nn];

// ---------------- PTX helpers ----------------
__device__ __forceinline__ void mma16816(float* c, const uint32_t* a, uint32_t b0, uint32_t b1) {
    asm volatile(
        "mma.sync.aligned.m16n8k16.row.col.f32.f16.f16.f32 "
        "{%0,%1,%2,%3}, {%4,%5,%6,%7}, {%8,%9}, {%0,%1,%2,%3};"
        : "+f"(c[0]), "+f"(c[1]), "+f"(c[2]), "+f"(c[3])
        : "r"(a[0]), "r"(a[1]), "r"(a[2]), "r"(a[3]), "r"(b0), "r"(b1));
}
__device__ __forceinline__ void ldm_x4(uint32_t* r, uint32_t addr) {
    asm volatile("ldmatrix.sync.aligned.m8n8.x4.shared.b16 {%0,%1,%2,%3}, [%4];"
                 : "=r"(r[0]), "=r"(r[1]), "=r"(r[2]), "=r"(r[3]) : "r"(addr));
}
__device__ __forceinline__ void cp16(uint32_t dst, const void* src) {
    asm volatile("cp.async.ca.shared.global [%0], [%1], 16;" :: "r"(dst), "l"(src));
}
__device__ __forceinline__ void cp_commit() { asm volatile("cp.async.commit_group;"); }
template <int N> __device__ __forceinline__ void cp_wait() {
    asm volatile("cp.async.wait_group %0;" :: "n"(N));
}

// ================== prep: x -> fp16 ==================
__global__ __launch_bounds__(256) void prep_x_kernel(const float* __restrict__ x) {
    int idx = blockIdx.x * 256 + threadIdx.x;          // float4 index
    float4 v = ((const float4*)x)[idx];
    __half2 hi01 = __floats2half2_rn(v.x, v.y);
    __half2 hi23 = __floats2half2_rn(v.z, v.w);
    ((__half2*)g_xh)[idx * 2] = hi01;
    ((__half2*)g_xh)[idx * 2 + 1] = hi23;
}

// ================== prep: W^T split fp16 [h][u][f] ==================
__global__ __launch_bounds__(256) void prep_wt_kernel(const float* __restrict__ W) {
    int idx = blockIdx.x * 256 + threadIdx.x;
    int f = idx & 255, u = (idx >> 8) & 255, h = idx >> 16;
    float w = W[((size_t)(h * 256 + f)) * 256 + u];
    __half hi = __float2half_rn(w);
    __half lo = __float2half_rn(w - __half2float(hi));
    size_t o = ((size_t)(h * 256 + u)) * 256 + f;
    g_wt_hi[o] = hi;
    g_wt_lo[o] = lo;
}

// ================== proj: h = xh @ (WH + WL)  — 2 MMA terms ==================
// dyn smem: buf[2] x {A, Wh, Wl} each 128 x STRIDE halves (30720 B/buf); sred after
#define PBUF (3 * 128 * STRIDE * 2)                    // 30720 B per buffer
#define P_SMEM (2 * PBUF + 4096)

__global__ __launch_bounds__(256) void proj_mma_kernel(const float* __restrict__ a_src,
                                                       const float* __restrict__ a_dst) {
    extern __shared__ __align__(16) char dyn[];
    float* sred = (float*)(dyn + 2 * PBUF);

    int tid = threadIdx.x;
    int warp = tid >> 5, lane = tid & 31;
    int warp_m = warp & 3, warp_n = warp >> 2;
    int bh = blockIdx.z, b = bh >> 2, h = bh & 3;
    int i0 = blockIdx.x * 128, u0 = blockIdx.y * 128;

    uint32_t smb = (uint32_t)__cvta_generic_to_shared(dyn);
    int row = tid >> 1, seg = tid & 1;

    auto issue = [&](int st, int bufi) {
        int f0 = st * 32;
        uint32_t base = smb + bufi * PBUF + row * (STRIDE * 2) + seg * 32;
        const __half* gA  = g_xh + ((size_t)(b * Nn + i0 + row)) * Ff + f0 + seg * 16;
        const __half* gWh = g_wt_hi + ((size_t)(h * 256 + u0 + row)) * 256 + f0 + seg * 16;
        const __half* gWl = g_wt_lo + ((size_t)(h * 256 + u0 + row)) * 256 + f0 + seg * 16;
        cp16(base, gA);                 cp16(base + 16, gA + 8);
        cp16(base + 10240, gWh);        cp16(base + 10240 + 16, gWh + 8);
        cp16(base + 20480, gWl);        cp16(base + 20480 + 16, gWl + 8);
    };

    float acc[2][8][4];
#pragma unroll
    for (int mt = 0; mt < 2; mt++)
#pragma unroll
        for (int nt = 0; nt < 8; nt++)
#pragma unroll
            for (int q = 0; q < 4; q++) acc[mt][nt][q] = 0.f;

    issue(0, 0);
    cp_commit();

    uint32_t a_off = (uint32_t)(warp_m * 32 + (lane & 15)) * (STRIDE * 2) + ((lane >> 4) * 8) * 2;
    uint32_t b_off = (uint32_t)(warp_n * 64 + (lane & 7)) * (STRIDE * 2) + ((lane >> 3) * 8) * 2;

    for (int st = 0; st < 8; st++) {
        if (st < 7) { issue(st + 1, (st + 1) & 1); cp_commit(); cp_wait<1>(); }
        else cp_wait<0>();
        __syncthreads();

        uint32_t bb = smb + (st & 1) * PBUF;
        uint32_t aH[2][2][4];
#pragma unroll
        for (int mt = 0; mt < 2; mt++)
#pragma unroll
            for (int kk = 0; kk < 2; kk++)
                ldm_x4(aH[mt][kk], bb + a_off + mt * 16 * (STRIDE * 2) + kk * 32);
#pragma unroll
        for (int nt = 0; nt < 8; nt++) {
            uint32_t bH[4], bL[4];
            uint32_t bd = bb + 10240 + b_off + nt * 8 * (STRIDE * 2);
            ldm_x4(bH, bd);
            ldm_x4(bL, bd + 10240);
#pragma unroll
            for (int kk = 0; kk < 2; kk++)
#pragma unroll
                for (int mt = 0; mt < 2; mt++) {
                    mma16816(acc[mt][nt], aH[mt][kk], bH[2 * kk], bH[2 * kk + 1]);
                    mma16816(acc[mt][nt], aH[mt][kk], bL[2 * kk], bL[2 * kk + 1]);
                }
        }
        __syncthreads();
    }

    // ---- epilogue A: partial src/dst dots ----
    {
        float s1[4] = {0.f, 0.f, 0.f, 0.f};
        float s2[4] = {0.f, 0.f, 0.f, 0.f};
#pragma unroll
        for (int nt = 0; nt < 8; nt++) {
            int u = u0 + warp_n * 64 + nt * 8 + (lane & 3) * 2;
            float2 as = *(const float2*)&a_src[h * 256 + u];
            float2 ad = *(const float2*)&a_dst[h * 256 + u];
#pragma unroll
            for (int mt = 0; mt < 2; mt++) {
                s1[mt * 2 + 0] += acc[mt][nt][0] * as.x + acc[mt][nt][1] * as.y;
                s1[mt * 2 + 1] += acc[mt][nt][2] * as.x + acc[mt][nt][3] * as.y;
                s2[mt * 2 + 0] += acc[mt][nt][0] * ad.x + acc[mt][nt][1] * ad.y;
                s2[mt * 2 + 1] += acc[mt][nt][2] * ad.x + acc[mt][nt][3] * ad.y;
            }
        }
#pragma unroll
        for (int q = 0; q < 4; q++) {
            s1[q] += __shfl_xor_sync(0xffffffffu, s1[q], 1);
            s1[q] += __shfl_xor_sync(0xffffffffu, s1[q], 2);
            s2[q] += __shfl_xor_sync(0xffffffffu, s2[q], 1);
            s2[q] += __shfl_xor_sync(0xffffffffu, s2[q], 2);
        }
        if ((lane & 3) == 0) {
#pragma unroll
            for (int q = 0; q < 4; q++) {
                int r = warp_m * 32 + (q >> 1) * 16 + (q & 1) * 8 + (lane >> 2);
                sred[(0 * 2 + warp_n) * 128 + r] = s1[q];
                sred[(2 + warp_n) * 128 + r] = s2[q];
            }
        }
    }
    __syncthreads();
    if (tid < 128) {
        size_t o = (size_t)blockIdx.y * (BHt * Nn) + bh * Nn + i0 + tid;
        g_srcp[o] = sred[0 * 128 + tid] + sred[1 * 128 + tid];
        g_dstp[o] = sred[2 * 128 + tid] + sred[3 * 128 + tid];
    }
    __syncthreads();

    // ---- epilogue B: fp16 transpose restage -> g_vt [u][n] ----
    __half (*tr)[136] = (__half (*)[136])dyn;
#pragma unroll
    for (int mt = 0; mt < 2; mt++) {
        int i_loc = warp_m * 32 + mt * 16 + (lane >> 2);
#pragma unroll
        for (int nt = 0; nt < 8; nt++) {
            int u_loc = warp_n * 64 + nt * 8 + (lane & 3) * 2;
            tr[u_loc][i_loc]         = __float2half_rn(acc[mt][nt][0]);
            tr[u_loc + 1][i_loc]     = __float2half_rn(acc[mt][nt][1]);
            tr[u_loc][i_loc + 8]     = __float2half_rn(acc[mt][nt][2]);
            tr[u_loc + 1][i_loc + 8] = __float2half_rn(acc[mt][nt][3]);
        }
    }
    __syncthreads();
    {
        const float4* srcp = (const float4*)&tr[row][seg * 64];
        float4* dstp = (float4*)&g_vt[((size_t)bh * Uu + u0 + row) * Nn + i0 + seg * 64];
#pragma unroll
        for (int k = 0; k < 8; k++) dstp[k] = srcp[k];
    }
}

// ================== prep: combine partials, P/Q/R/S/thr fp16 per (b,h) ==================
__global__ __launch_bounds__(1024) void prep_pqrs_kernel() {
    __shared__ float red[1024];
    int bh = blockIdx.x, tid = threadIdx.x;
    int row = bh * Nn + tid;
    float d = g_dstp[row] + g_dstp[BHt * Nn + row];
    float sv = g_srcp[row] + g_srcp[BHt * Nn + row];
    red[tid] = d;
    __syncthreads();
    for (int s = 512; s > 0; s >>= 1) {
        if (tid < s) red[tid] = fmaxf(red[tid], red[tid + s]);
        __syncthreads();
    }
    float dmax = red[0];
    g_Qh[row] = __float2half_rn(__expf(d - dmax));
    g_Sh[row] = __float2half_rn(__expf(0.2f * (d - dmax)));
    g_Dh[row] = __float2half_rn(d);
    float T = sv + dmax;
    float m = fmaxf(T, 0.2f * T);
    g_Ph[row] = __float2half_rn(__expf(T - m));
    g_Rh[row] = __float2half_rn(__expf(0.2f * T - m));
    g_Th[row] = __float2half_rn(-sv);
}

// ================== attention (R8 known-good): half2 weight-gen + ldmatrix V ==================
__global__ __launch_bounds__(256) void attn_mma_kernel(float* __restrict__ out) {
    __shared__ __align__(16) __half VT[2][128][STRIDE];
    __shared__ __half Dsh[Nn], Qsh[Nn], Ssh[Nn];
    __shared__ __half Pn[128], Rn[128], Tn[128];

    int tid = threadIdx.x;
    int warp = tid >> 5, lane = tid & 31;
    int warp_m = warp & 3, warp_n = warp >> 2;
    int bh = blockIdx.z, b = bh >> 2, h = bh & 3;
    int i0 = blockIdx.x * 128, u0 = blockIdx.y * 128;

    for (int j = tid; j < Nn; j += 256) {
        Dsh[j] = g_Dh[bh * Nn + j];
        Qsh[j] = g_Qh[bh * Nn + j];
        Ssh[j] = g_Sh[bh * Nn + j];
    }
    if (tid < 128) {
        Pn[tid] = g_Ph[bh * Nn + i0 + tid];
        Rn[tid] = g_Rh[bh * Nn + i0 + tid];
        Tn[tid] = g_Th[bh * Nn + i0 + tid];
    }

    int row = tid >> 1, seg = tid & 1;
    uint32_t vt0 = (uint32_t)__cvta_generic_to_shared(&VT[0][0][0]);
    const uint32_t VBUF = 128 * STRIDE * 2;

    auto issue = [&](int st, int bufi) {
        int j0 = st * 32;
        uint32_t d = vt0 + bufi * VBUF + row * (STRIDE * 2) + seg * 32;
        const __half* g = g_vt + ((size_t)bh * Uu + u0 + row) * Nn + j0 + seg * 16;
        cp16(d, g);
        cp16(d + 16, g + 8);
    };

    float acc[2][8][4];
#pragma unroll
    for (int mt = 0; mt < 2; mt++)
#pragma unroll
        for (int nt = 0; nt < 8; nt++)
#pragma unroll
            for (int q = 0; q < 4; q++) acc[mt][nt][q] = 0.f;
    float rs[4] = {0.f, 0.f, 0.f, 0.f};

    issue(0, 0);
    cp_commit();
    __syncthreads();

    __half2 Pv[4], Rv[4], Tv[4];
#pragma unroll
    for (int q = 0; q < 4; q++) {
        int r = warp_m * 32 + (q >> 1) * 16 + (q & 1) * 8 + (lane >> 2);
        Pv[q] = __half2half2(Pn[r]);
        Rv[q] = __half2half2(Rn[r]);
        Tv[q] = __half2half2(Tn[r]);
    }

    uint32_t b_off = (uint32_t)(warp_n * 64 + (lane & 7)) * (STRIDE * 2) + ((lane >> 3) * 8) * 2;

    for (int st = 0; st < 32; st++) {
        int j0 = st * 32;
        if (st < 31) { issue(st + 1, (st + 1) & 1); cp_commit(); cp_wait<1>(); }
        else cp_wait<0>();
        __syncthreads();

        uint32_t bb = vt0 + (st & 1) * VBUF;
        uint32_t bfr[8][4];
#pragma unroll
        for (int nt = 0; nt < 8; nt++)
            ldm_x4(bfr[nt], bb + b_off + nt * 8 * (STRIDE * 2));

#pragma unroll
        for (int kk = 0; kk < 2; kk++) {
            int c = j0 + kk * 16 + (lane & 3) * 2;
            __half2 Qa = *(const __half2*)&Qsh[c], Qb = *(const __half2*)&Qsh[c + 8];
            __half2 Sa = *(const __half2*)&Ssh[c], Sb = *(const __half2*)&Ssh[c + 8];
            __half2 Da = *(const __half2*)&Dsh[c], Db = *(const __half2*)&Dsh[c + 8];

            uint32_t aW[2][4];
#pragma unroll
            for (int mt = 0; mt < 2; mt++) {
#pragma unroll
                for (int dq = 0; dq < 2; dq++) {
                    int q = mt * 2 + dq;
                    __half2 mA = __hge2(Da, Tv[q]);
                    __half2 wPa = __hmul2(Pv[q], Qa);
                    __half2 wRa = __hmul2(Rv[q], Sa);
                    __half2 wa = __hfma2(__hsub2(wPa, wRa), mA, wRa);
                    __half2 mB = __hge2(Db, Tv[q]);
                    __half2 wPb = __hmul2(Pv[q], Qb);
                    __half2 wRb = __hmul2(Rv[q], Sb);
                    __half2 wb = __hfma2(__hsub2(wPb, wRb), mB, wRb);
                    aW[mt][dq]     = *reinterpret_cast<uint32_t*>(&wa);
                    aW[mt][dq + 2] = *reinterpret_cast<uint32_t*>(&wb);
                    __half2 hsum = __hadd2(wa, wb);
                    float2 f = __half22float2(hsum);
                    rs[q] += f.x + f.y;
                }
            }
#pragma unroll
            for (int nt = 0; nt < 8; nt++)
#pragma unroll
                for (int mt = 0; mt < 2; mt++)
                    mma16816(acc[mt][nt], aW[mt], bfr[nt][2 * kk], bfr[nt][2 * kk + 1]);
        }
        __syncthreads();
    }

#pragma unroll
    for (int q = 0; q < 4; q++) {
        rs[q] += __shfl_xor_sync(0xffffffffu, rs[q], 1);
        rs[q] += __shfl_xor_sync(0xffffffffu, rs[q], 2);
        rs[q] = 1.0f / rs[q];
    }

#pragma unroll
    for (int mt = 0; mt < 2; mt++) {
        int i_lo = i0 + warp_m * 32 + mt * 16 + (lane >> 2);
        float inv0 = rs[mt * 2], inv1 = rs[mt * 2 + 1];
#pragma unroll
        for (int nt = 0; nt < 8; nt++) {
            int u = u0 + warp_n * 64 + nt * 8 + (lane & 3) * 2;
            size_t o0 = ((size_t)(b * Nn + i_lo)) * (Hh * Uu) + h * Uu + u;
            size_t o1 = ((size_t)(b * Nn + i_lo + 8)) * (Hh * Uu) + h * Uu + u;
            *(float2*)&out[o0] = make_float2(acc[mt][nt][0] * inv0, acc[mt][nt][1] * inv0);
            *(float2*)&out[o1] = make_float2(acc[mt][nt][2] * inv1, acc[mt][nt][3] * inv1);
        }
    }
}

// ---------------------------------------------------------------------------
extern "C" void kernel_launch(void* const* d_in, const int* in_sizes, int n_in,
                              void* d_out, int out_size) {
    (void)in_sizes; (void)n_in; (void)out_size;
    const float* x     = (const float*)d_in[0];
    const float* W     = (const float*)d_in[1];
    const float* a_src = (const float*)d_in[2];
    const float* a_dst = (const float*)d_in[3];
    float* out = (float*)d_out;

    cudaFuncSetAttribute(proj_mma_kernel, cudaFuncAttributeMaxDynamicSharedMemorySize, P_SMEM);

    prep_x_kernel<<<(Bb * Nn * Ff) / 1024, 256>>>(x);
    prep_wt_kernel<<<(Hh * Uu * Ff) / 256, 256>>>(W);
    proj_mma_kernel<<<dim3(8, 2, BHt), 256, P_SMEM>>>(a_src, a_dst);
    prep_pqrs_kernel<<<BHt, 1024>>>();
    attn_mma_kernel<<<dim3(8, 2, BHt), 256>>>(out);
}